// round 1
// baseline (speedup 1.0000x reference)
#include <cuda_runtime.h>

#define DD 128
#define TM 128
#define TK 16
#define MAX_R 8
#define MAX_N 50000

// Scratch for XW[r] = X @ W[r], r = 0..7. 8*50000*128 floats = 204.8 MB.
// __device__ global (allocation inside kernel_launch is forbidden).
__device__ float g_xw[(size_t)MAX_R * MAX_N * DD];

__device__ __forceinline__ unsigned long long fma2(unsigned long long a,
                                                   unsigned long long b,
                                                   unsigned long long c) {
    unsigned long long d;
    asm("fma.rn.f32x2 %0, %1, %2, %3;" : "=l"(d) : "l"(a), "l"(b), "l"(c));
    return d;
}

__device__ __forceinline__ unsigned long long pack2(float lo, float hi) {
    unsigned long long r;
    asm("mov.b64 %0, {%1, %2};" : "=l"(r) : "f"(lo), "f"(hi));
    return r;
}

// Computes C = X @ Wg for g in [0, R]:
//   g < R  : Wg = W[g],  C = g_xw[g]   (per-relation transform)
//   g == R : Wg = W0,    C = out       (self-connection, also initializes out)
// Tile: 128 rows x 128 cols (full D_OUT), K looped in chunks of 16.
// 256 threads, each computes an 8x8 microtile as 4x8 f32x2 pairs (paired
// along M so the f32x2 'a' operand is a natural contiguous 8B LDS load).
__global__ __launch_bounds__(256, 2)
void gemm_kernel(const float* __restrict__ X, const float* __restrict__ W,
                 const float* __restrict__ W0, float* __restrict__ out,
                 int N, int R)
{
    __shared__ float As[TK][TM + 4];   // A transposed: As[k][m], pad keeps 8B align + 2-way max conflicts
    __shared__ float Bs[TK][DD];       // B natural:   Bs[k][n]

    const int g = blockIdx.y;
    const int row0 = blockIdx.x * TM;
    const float* Wg = (g < R) ? (W + (size_t)g * DD * DD) : W0;
    float* Cg = (g < R) ? (g_xw + (size_t)g * N * DD) : out;

    const int t = threadIdx.x;
    const int tx = t & 15;          // n-group: cols tx + j*16, j=0..7 (conflict-free LDS.32)
    const int ty = t >> 4;          // m-group: rows ty*8 .. ty*8+7
    const int ld_m  = t >> 2;       // A-load row within tile (and +64)
    const int ld_k4 = (t & 3) * 4;  // A-load k offset (float4)
    const int ld_kb = t >> 5;       // B-load k row (and +8)
    const int ld_n4 = (t & 31) * 4; // B-load col (float4)

    unsigned long long c2[4][8];
    #pragma unroll
    for (int i = 0; i < 4; ++i)
        #pragma unroll
        for (int j = 0; j < 8; ++j) c2[i][j] = 0ULL;   // f32x2 (0,0)

    for (int kt = 0; kt < DD / TK; ++kt) {
        // Load A tile (transposed into smem), guard row tail (N % 128 != 0)
        #pragma unroll
        for (int h = 0; h < 2; ++h) {
            int m = ld_m + h * 64;
            int grow = row0 + m;
            float4 v = make_float4(0.f, 0.f, 0.f, 0.f);
            if (grow < N)
                v = *(const float4*)(X + (size_t)grow * DD + kt * TK + ld_k4);
            As[ld_k4 + 0][m] = v.x;
            As[ld_k4 + 1][m] = v.y;
            As[ld_k4 + 2][m] = v.z;
            As[ld_k4 + 3][m] = v.w;
        }
        // Load B tile (natural layout, fully coalesced float4)
        #pragma unroll
        for (int h = 0; h < 2; ++h) {
            int k = ld_kb + h * 8;
            *(float4*)&Bs[k][ld_n4] =
                *(const float4*)(Wg + (size_t)(kt * TK + k) * DD + ld_n4);
        }
        __syncthreads();

        #pragma unroll
        for (int k = 0; k < TK; ++k) {
            unsigned long long a2[4];
            #pragma unroll
            for (int i = 0; i < 4; ++i)   // 8B loads, 2 distinct addrs/warp -> broadcast
                a2[i] = *(const unsigned long long*)&As[k][ty * 8 + i * 2];
            #pragma unroll
            for (int j = 0; j < 8; ++j) {
                float bv = Bs[k][tx + j * 16];          // consecutive banks -> conflict-free
                unsigned long long bb = pack2(bv, bv);  // dup for f32x2
                #pragma unroll
                for (int i = 0; i < 4; ++i)
                    c2[i][j] = fma2(a2[i], bb, c2[i][j]);  // 32 FFMA2 = 64 FMA per k
            }
        }
        __syncthreads();
    }

    // Epilogue: unpack f32x2 pairs (rows r0, r0+1), guarded store
    #pragma unroll
    for (int i = 0; i < 4; ++i) {
        int r0 = row0 + ty * 8 + i * 2;
        #pragma unroll
        for (int j = 0; j < 8; ++j) {
            int col = tx + j * 16;
            float2 v;
            asm("mov.b64 {%0, %1}, %2;" : "=f"(v.x), "=f"(v.y) : "l"(c2[i][j]));
            if (r0 < N)     Cg[(size_t)r0 * DD + col]       = v.x;
            if (r0 + 1 < N) Cg[(size_t)(r0 + 1) * DD + col] = v.y;
        }
    }
}

// One warp per edge: gather XW[rel, src] (512B), scale by inv_norm[rel, dst],
// vector-reduce into out[dst]. red.global.add.v4.f32 quarters atomic op count
// vs scalar atomicAdd (25.6M ops instead of 102.4M).
__global__ void scatter_kernel(const int* __restrict__ esrc,
                               const int* __restrict__ edst,
                               const int* __restrict__ erel,
                               const float* __restrict__ inv_norm,
                               float* __restrict__ out, int E, int N)
{
    int e = blockIdx.x * (blockDim.x >> 5) + (threadIdx.x >> 5);
    if (e >= E) return;
    int lane = threadIdx.x & 31;

    int s = __ldg(&esrc[e]);     // same addr across warp -> single broadcast transaction
    int d = __ldg(&edst[e]);
    int r = __ldg(&erel[e]);
    float scale = __ldg(&inv_norm[(size_t)r * N + d]);

    const float4* row = (const float4*)(g_xw + ((size_t)r * N + s) * DD);
    float4 v = __ldg(&row[lane]);                       // 32 lanes x 16B = full 512B row

    float* o = out + (size_t)d * DD + lane * 4;         // 16B-aligned
    asm volatile("red.global.add.v4.f32 [%0], {%1, %2, %3, %4};"
                 :: "l"(o),
                    "f"(v.x * scale), "f"(v.y * scale),
                    "f"(v.z * scale), "f"(v.w * scale)
                 : "memory");
}

extern "C" void kernel_launch(void* const* d_in, const int* in_sizes, int n_in,
                              void* d_out, int out_size)
{
    const float* X        = (const float*)d_in[0];
    const float* W        = (const float*)d_in[1];
    const float* W0       = (const float*)d_in[2];
    const float* inv_norm = (const float*)d_in[3];
    const int*   esrc     = (const int*)d_in[4];
    const int*   edst     = (const int*)d_in[5];
    const int*   erel     = (const int*)d_in[6];
    float* out = (float*)d_out;

    int N = in_sizes[0] / DD;            // 50000
    int R = in_sizes[1] / (DD * DD);     // 8
    int E = in_sizes[4];                 // 800000

    // Phase 1: XW[r] for all relations + out = X @ W0 (initializes out fully).
    dim3 grid((N + TM - 1) / TM, R + 1);
    gemm_kernel<<<grid, 256>>>(X, W, W0, out, N, R);

    // Phase 2: edge scatter-accumulate into out (stream-ordered after phase 1).
    int epb = 256 / 32;   // 8 edges (warps) per 256-thread block
    scatter_kernel<<<(E + epb - 1) / epb, 256>>>(esrc, edst, erel, inv_norm, out, E, N);
}